// round 2
// baseline (speedup 1.0000x reference)
#include <cuda_runtime.h>

#define NN 100000
#define EE 1000000
#define CC 64
#define OUTC 40
#define NB 98   // ceil(NN/1024)

// ---------------- device scratch (static; no allocation allowed) ----------------
__device__ int   g_is64;          // 1 if edge_index is int64, 0 if int32
__device__ int   g_count[NN];
__device__ int   g_cursor[NN];
__device__ int   g_rowptr[NN + 1];
__device__ int   g_bsum[NB];
__device__ int   g_srcs[EE];
__device__ float g_norm[EE];
__device__ float g_dinv[NN];
__device__ float g_h1[NN * CC];
__device__ float g_h2[NN * CC];

// ---------------- edge index dtype detection ----------------
__global__ void k_detect(const void* ei) {
    // int64-view of int32 data combines adjacent int32s -> huge values.
    const long long* p = (const long long*)ei;
    int is64 = 1;
    for (int i = 0; i < 16; i++) {
        long long v = p[i];
        if (v < 0 || v >= NN) { is64 = 0; break; }
    }
    g_is64 = is64;
}

__device__ __forceinline__ int edge_src(const void* ei, int e) {
    if (g_is64) return (int)((const long long*)ei)[e];
    return ((const int*)ei)[e];
}
__device__ __forceinline__ int edge_dst(const void* ei, int e) {
    if (g_is64) return (int)((const long long*)ei)[EE + e];
    return ((const int*)ei)[EE + e];
}

// ---------------- CSR construction ----------------
__global__ void k_zero() {
    int i = blockIdx.x * 256 + threadIdx.x;
    if (i < NN) { g_count[i] = 0; g_cursor[i] = 0; }
}

__global__ void k_hist(const void* __restrict__ ei) {
    int e = blockIdx.x * 256 + threadIdx.x;
    if (e < EE) atomicAdd(&g_count[edge_dst(ei, e)], 1);
}

__global__ void k_scanA() {
    __shared__ int s[1024];
    int i = blockIdx.x * 1024 + threadIdx.x;
    int v = (i < NN) ? g_count[i] : 0;
    s[threadIdx.x] = v;
    __syncthreads();
    for (int off = 1; off < 1024; off <<= 1) {
        int t = (threadIdx.x >= off) ? s[threadIdx.x - off] : 0;
        __syncthreads();
        s[threadIdx.x] += t;
        __syncthreads();
    }
    if (i < NN) g_rowptr[i] = s[threadIdx.x] - v;   // exclusive within block
    if (threadIdx.x == 1023) g_bsum[blockIdx.x] = s[1023];
}

__global__ void k_scanB() {
    int acc = 0;
    for (int b = 0; b < NB; b++) { int v = g_bsum[b]; g_bsum[b] = acc; acc += v; }
}

__global__ void k_scanC() {
    int i = blockIdx.x * 256 + threadIdx.x;
    if (i < NN) {
        g_rowptr[i] += g_bsum[i >> 10];
        g_dinv[i] = rsqrtf((float)g_count[i] + 1.0f);
    }
    if (i == 0) g_rowptr[NN] = EE;
}

__global__ void k_fill(const void* __restrict__ ei) {
    int e = blockIdx.x * 256 + threadIdx.x;
    if (e < EE) {
        int s = edge_src(ei, e);
        int d = edge_dst(ei, e);
        int pos = g_rowptr[d] + atomicAdd(&g_cursor[d], 1);
        g_srcs[pos] = s;
        g_norm[pos] = g_dinv[s] * g_dinv[d];
    }
}

// ---------------- dense GEMM: out[N,OUTF] = in[N,64] @ W[64,OUTF] (+bias)(relu) ----------------
template <int OUTF, int CHUNK, bool HASB, bool RELU>
__global__ __launch_bounds__(256)
void k_gemm(const float* __restrict__ in, const float* __restrict__ W,
            const float* __restrict__ bias, float* __restrict__ out) {
    __shared__ __align__(16) float Ws[CC * OUTF];
    int tid = threadIdx.x;
    for (int idx = tid; idx < CC * OUTF; idx += 256) Ws[idx] = W[idx];
    __syncthreads();

    int row = blockIdx.x * 256 + tid;
    if (row >= NN) return;

    float x[CC];
    const float4* xr = (const float4*)(in + (size_t)row * CC);
#pragma unroll
    for (int j = 0; j < CC / 4; j++) {
        float4 t = xr[j];
        x[4 * j] = t.x; x[4 * j + 1] = t.y; x[4 * j + 2] = t.z; x[4 * j + 3] = t.w;
    }

#pragma unroll
    for (int c = 0; c < OUTF / CHUNK; c++) {
        float acc[CHUNK];
#pragma unroll
        for (int j = 0; j < CHUNK; j++) acc[j] = 0.f;
#pragma unroll
        for (int k = 0; k < CC; k++) {
            float xk = x[k];
            const float4* w4 = (const float4*)(Ws + k * OUTF + c * CHUNK);
#pragma unroll
            for (int j = 0; j < CHUNK / 4; j++) {
                float4 w = w4[j];
                acc[4 * j]     = fmaf(xk, w.x, acc[4 * j]);
                acc[4 * j + 1] = fmaf(xk, w.y, acc[4 * j + 1]);
                acc[4 * j + 2] = fmaf(xk, w.z, acc[4 * j + 2]);
                acc[4 * j + 3] = fmaf(xk, w.w, acc[4 * j + 3]);
            }
        }
#pragma unroll
        for (int j = 0; j < CHUNK; j++) {
            float v = acc[j];
            if (HASB) v += __ldg(&bias[c * CHUNK + j]);
            if (RELU) v = fmaxf(v, 0.f);
            out[(size_t)row * OUTF + c * CHUNK + j] = v;
        }
    }
}

// ---------------- pull-style aggregation: out = norm-weighted gather-sum + self + bias ----------------
template <bool RELU>
__global__ __launch_bounds__(256)
void k_agg(const float* __restrict__ h, const float* __restrict__ bias,
           float* __restrict__ out) {
    int node = blockIdx.x * 8 + (threadIdx.x >> 5);
    if (node >= NN) return;
    int lane = threadIdx.x & 31;

    float di = g_dinv[node];
    float self = di * di;
    float acc0 = h[(size_t)node * CC + lane] * self;
    float acc1 = h[(size_t)node * CC + 32 + lane] * self;

    int beg = g_rowptr[node];
    int end = g_rowptr[node + 1];
    for (int e = beg; e < end; e++) {
        int   s  = g_srcs[e];
        float nm = g_norm[e];
        const float* hs = h + (size_t)s * CC;
        acc0 = fmaf(hs[lane], nm, acc0);
        acc1 = fmaf(hs[32 + lane], nm, acc1);
    }
    acc0 += __ldg(&bias[lane]);
    acc1 += __ldg(&bias[32 + lane]);
    if (RELU) { acc0 = fmaxf(acc0, 0.f); acc1 = fmaxf(acc1, 0.f); }
    out[(size_t)node * CC + lane] = acc0;
    out[(size_t)node * CC + 32 + lane] = acc1;
}

// ---------------- launcher ----------------
extern "C" void kernel_launch(void* const* d_in, const int* in_sizes, int n_in,
                              void* d_out, int out_size) {
    const float* x   = (const float*)d_in[0];
    const void*  ei  = d_in[1];
    const float* W1  = (const float*)d_in[2];
    const float* b1  = (const float*)d_in[3];
    const float* W2  = (const float*)d_in[4];
    const float* b2  = (const float*)d_in[5];
    const float* Wm1 = (const float*)d_in[6];
    const float* bm1 = (const float*)d_in[7];
    const float* Wm2 = (const float*)d_in[8];
    const float* bm2 = (const float*)d_in[9];
    float* out = (float*)d_out;

    void *p1 = nullptr, *p2 = nullptr;
    cudaGetSymbolAddress(&p1, g_h1);
    cudaGetSymbolAddress(&p2, g_h2);
    float* h1 = (float*)p1;
    float* h2 = (float*)p2;

    const int GN = (NN + 255) / 256;   // node-grid
    const int GE = (EE + 255) / 256;   // edge-grid
    const int GA = (NN + 7) / 8;       // agg-grid (8 nodes / block)

    // CSR build (per launch; deterministic work)
    k_detect<<<1, 1>>>(ei);
    k_zero <<<GN, 256>>>();
    k_hist <<<GE, 256>>>(ei);
    k_scanA<<<NB, 1024>>>();
    k_scanB<<<1, 1>>>();
    k_scanC<<<GN, 256>>>();
    k_fill <<<GE, 256>>>(ei);

    // GCN conv 1: h1 = x@W1 ; h2 = relu(agg(h1) + b1)
    k_gemm<64, 16, false, false><<<GN, 256>>>(x, W1, nullptr, h1);
    k_agg<true><<<GA, 256>>>(h1, b1, h2);

    // GCN conv 2: h1 = h2@W2 ; h2 = agg(h1) + b2
    k_gemm<64, 16, false, false><<<GN, 256>>>(h2, W2, nullptr, h1);
    k_agg<false><<<GA, 256>>>(h1, b2, h2);

    // MLP: h1 = relu(h2@Wm1 + bm1) ; out = h1@Wm2 + bm2
    k_gemm<64, 16, true, true ><<<GN, 256>>>(h2, Wm1, bm1, h1);
    k_gemm<40, 20, true, false><<<GN, 256>>>(h1, Wm2, bm2, out);
}